// round 1
// baseline (speedup 1.0000x reference)
#include <cuda_runtime.h>
#include <cuda_fp16.h>
#include <cstdint>

#define B_  256
#define T_  512
#define I_  24
#define H_  128
#define G_  512           // 4*H
#define BT_ (B_*T_)       // 131072
#define BB_ 4             // batch rows per scan block

static const size_t Y1SZ_ = (size_t)BT_ * 2 * H_;   // 33,554,432

// ---------------- scratch (no cudaMalloc allowed) ----------------
__device__ float  g_gx[2][(size_t)BT_ * G_];        // 2 x 256 MB
__device__ float  g_y0[(size_t)BT_ * 2 * H_];       // 128 MB
__device__ __half g_y0h[(size_t)BT_ * 2 * H_];      // 64 MB
__device__ __half g_xh[(size_t)BT_ * 32];           // x padded 24->32, fp16
__device__ __half g_w0h[2][G_ * 32];                // w_ih layer0 padded, fp16
__device__ __half g_w1h[2][G_ * 256];               // w_ih layer1, fp16

__device__ __forceinline__ float sigm(float x)   { return 1.f / (1.f + __expf(-x)); }
__device__ __forceinline__ float tanh_f(float x) { return 2.f / (1.f + __expf(-2.f * x)) - 1.f; }

// ---------------- conversion kernels ----------------
__global__ void conv_x_kernel(const float* __restrict__ x) {
    int idx = blockIdx.x * 256 + threadIdx.x;
    if (idx < BT_ * 32) {
        int r = idx >> 5, i = idx & 31;
        g_xh[idx] = (i < I_) ? __float2half(x[r * I_ + i]) : __float2half(0.f);
    }
}

__global__ void conv_w_kernel(const float* __restrict__ w0f, const float* __restrict__ w0b,
                              const float* __restrict__ w1f, const float* __restrict__ w1b) {
    int idx = blockIdx.x * 256 + threadIdx.x;
    if (idx < 2 * G_ * 32) {
        int d = idx / (G_ * 32); int p = idx % (G_ * 32);
        int j = p >> 5, i = p & 31;
        const float* w = d ? w0b : w0f;
        g_w0h[d][p] = (i < I_) ? __float2half(w[j * I_ + i]) : __float2half(0.f);
    } else {
        int q = idx - 2 * G_ * 32;
        if (q < 2 * G_ * 256) {
            int d = q / (G_ * 256); int p = q % (G_ * 256);
            const float* w = d ? w1b : w1f;
            g_w1h[d][p] = __float2half(w[p]);
        }
    }
}

__global__ void conv_h_kernel() {
    size_t idx = (size_t)blockIdx.x * 256 + threadIdx.x;
    if (idx < (size_t)BT_ * 2 * H_) g_y0h[idx] = __float2half(g_y0[idx]);
}

// ---------------- input GEMM: gx[dir][t*B+b][j] = A[r] . W[dir][j] + bias ----------------
// A: [BT][K] fp16 row-major (r = b*T + t). W: [512][K] fp16 row-major (== col-major B for mma).
// fp16 x fp16 -> fp32 accum via mma.sync m16n8k16. Block tile 64(M) x 128(N), 8 warps.
__global__ __launch_bounds__(256) void gemm_gx_kernel(
    const float* __restrict__ biasf, const float* __restrict__ biasb, int K)
{
    const int dir = blockIdx.z;
    const __half* __restrict__ A = (K == 32) ? g_xh : g_y0h;
    const __half* __restrict__ W = (K == 32) ? g_w0h[dir] : g_w1h[dir];
    const float* __restrict__ bias = dir ? biasb : biasf;
    float* __restrict__ gx = g_gx[dir];

    const int tid  = threadIdx.x;
    const int lane = tid & 31;
    const int warp = tid >> 5;
    const int warpM = warp & 1;
    const int warpN = warp >> 1;
    const int m_base = blockIdx.x * 64 + warpM * 32;
    const int n_base = blockIdx.y * 128 + warpN * 32;
    const int g4 = lane >> 2;       // groupID
    const int tg = lane & 3;        // thread in group

    float acc[2][4][4];
    #pragma unroll
    for (int mf = 0; mf < 2; mf++)
        #pragma unroll
        for (int nf = 0; nf < 4; nf++)
            #pragma unroll
            for (int q = 0; q < 4; q++) acc[mf][nf][q] = 0.f;

    for (int k0 = 0; k0 < K; k0 += 16) {
        unsigned a[2][4];
        #pragma unroll
        for (int mf = 0; mf < 2; mf++) {
            const __half* Ap = A + (size_t)(m_base + mf * 16 + g4) * K + k0 + tg * 2;
            a[mf][0] = *(const unsigned*)(Ap);
            a[mf][1] = *(const unsigned*)(Ap + 8 * K);
            a[mf][2] = *(const unsigned*)(Ap + 8);
            a[mf][3] = *(const unsigned*)(Ap + 8 * K + 8);
        }
        #pragma unroll
        for (int nf = 0; nf < 4; nf++) {
            const __half* Wp = W + (size_t)(n_base + nf * 8 + g4) * K + k0 + tg * 2;
            unsigned b0 = *(const unsigned*)(Wp);
            unsigned b1 = *(const unsigned*)(Wp + 8);
            #pragma unroll
            for (int mf = 0; mf < 2; mf++) {
                asm volatile(
                    "mma.sync.aligned.m16n8k16.row.col.f32.f16.f16.f32 "
                    "{%0,%1,%2,%3}, {%4,%5,%6,%7}, {%8,%9}, {%0,%1,%2,%3};"
                    : "+f"(acc[mf][nf][0]), "+f"(acc[mf][nf][1]),
                      "+f"(acc[mf][nf][2]), "+f"(acc[mf][nf][3])
                    : "r"(a[mf][0]), "r"(a[mf][1]), "r"(a[mf][2]), "r"(a[mf][3]),
                      "r"(b0), "r"(b1));
            }
        }
    }

    // epilogue: add bias, scatter rows (r = b*T + t) to gx layout [t][b][j]
    #pragma unroll
    for (int mf = 0; mf < 2; mf++) {
        int m0 = m_base + mf * 16 + g4;
        #pragma unroll
        for (int nf = 0; nf < 4; nf++) {
            int n0 = n_base + nf * 8 + tg * 2;
            float bv0 = bias[n0], bv1 = bias[n0 + 1];
            int r = m0;
            int t = r & (T_ - 1); int bb = r >> 9;
            size_t o = ((size_t)t * B_ + bb) * G_ + n0;
            gx[o]     = acc[mf][nf][0] + bv0;
            gx[o + 1] = acc[mf][nf][1] + bv1;
            r = m0 + 8;
            t = r & (T_ - 1); bb = r >> 9;
            o = ((size_t)t * B_ + bb) * G_ + n0;
            gx[o]     = acc[mf][nf][2] + bv0;
            gx[o + 1] = acc[mf][nf][3] + bv1;
        }
    }
}

// ---------------- recurrent scan ----------------
// grid (64, 2): blockIdx.x = batch group (BB rows), blockIdx.y = direction.
// 512 threads. Matvec phase: thread j accumulates g[b][j] for b=0..3.
// Update phase: thread (k = tid&127, b = tid>>7) owns h[k],c[k] for its batch row.
// w_hh in smem as fp16 (k-major, conflict-free), fp32 FFMA accumulation.
__global__ __launch_bounds__(512) void lstm_scan_kernel(
    const float* __restrict__ whhf, const float* __restrict__ whhb,
    float* __restrict__ y1, float* __restrict__ hn, float* __restrict__ cn, int layer)
{
    extern __shared__ unsigned char smem_raw[];
    __half2* wsmT = (__half2*)smem_raw;                               // [64][512] half2
    float* hsm = (float*)(smem_raw + (size_t)G_ * (H_ / 2) * 4);      // [128*4]
    float* gsm = hsm + H_ * BB_;                                      // [512*4]

    const int tid = threadIdx.x;
    const int dir = blockIdx.y;
    const int b0  = blockIdx.x * BB_;
    const float* __restrict__ whh = dir ? whhb : whhf;
    const float* __restrict__ gx  = g_gx[dir];
    float* __restrict__ yout = layer ? y1 : g_y0;

    // stage w_hh -> smem fp16, layout wsmT[kk][j] (j contiguous: conflict-free reads)
    for (int p = tid; p < G_ * (H_ / 2); p += 512) {
        int j = p >> 6, kk = p & 63;
        float2 wv = *(const float2*)(whh + j * H_ + kk * 2);
        wsmT[kk * G_ + j] = __floats2half2_rn(wv.x, wv.y);
    }
    hsm[tid] = 0.f;
    float c = 0.f, h = 0.f;
    const int uk = tid & (H_ - 1);
    const int ub = tid >> 7;
    __syncthreads();

    const float4* hsm4 = (const float4*)hsm;
    float4* gsm4 = (float4*)gsm;

    for (int s = 0; s < T_; s++) {
        const int t = dir ? (T_ - 1 - s) : s;
        const float* gxp = gx + ((size_t)t * B_ + b0) * G_;
        // prefetch gx (consumed after the matvec -> latency hidden)
        float gx0 = gxp[tid], gx1 = gxp[G_ + tid], gx2 = gxp[2 * G_ + tid], gx3 = gxp[3 * G_ + tid];

        float a0 = 0.f, a1 = 0.f, a2 = 0.f, a3 = 0.f;
        #pragma unroll 16
        for (int kk = 0; kk < H_ / 2; kk++) {
            float2 wf = __half22float2(wsmT[kk * G_ + tid]);
            float4 h0 = hsm4[2 * kk];
            float4 h1 = hsm4[2 * kk + 1];
            a0 = fmaf(wf.x, h0.x, a0); a1 = fmaf(wf.x, h0.y, a1);
            a2 = fmaf(wf.x, h0.z, a2); a3 = fmaf(wf.x, h0.w, a3);
            a0 = fmaf(wf.y, h1.x, a0); a1 = fmaf(wf.y, h1.y, a1);
            a2 = fmaf(wf.y, h1.z, a2); a3 = fmaf(wf.y, h1.w, a3);
        }
        gsm4[tid] = make_float4(a0 + gx0, a1 + gx1, a2 + gx2, a3 + gx3);
        __syncthreads();   // matvec done (all hsm reads retired), gsm visible

        float gi = gsm[(0 * H_ + uk) * BB_ + ub];
        float gf = gsm[(1 * H_ + uk) * BB_ + ub];
        float gg = gsm[(2 * H_ + uk) * BB_ + ub];
        float go = gsm[(3 * H_ + uk) * BB_ + ub];
        float ii = sigm(gi), ff = sigm(gf), gv = tanh_f(gg), oo = sigm(go);
        c = fmaf(ff, c, ii * gv);
        h = oo * tanh_f(c);
        hsm[uk * BB_ + ub] = h;
        yout[((size_t)(b0 + ub) * T_ + t) * (2 * H_) + dir * H_ + uk] = h;
        __syncthreads();   // new h visible for next matvec
    }

    const int d = layer * 2 + dir;
    hn[((size_t)d * B_ + b0 + ub) * H_ + uk] = h;
    cn[((size_t)d * B_ + b0 + ub) * H_ + uk] = c;
}

// ---------------- launch ----------------
extern "C" void kernel_launch(void* const* d_in, const int* in_sizes, int n_in,
                              void* d_out, int out_size) {
    const float* x     = (const float*)d_in[0];
    const float* wih0f = (const float*)d_in[1];
    const float* whh0f = (const float*)d_in[2];
    const float* b0f   = (const float*)d_in[3];
    const float* wih0b = (const float*)d_in[4];
    const float* whh0b = (const float*)d_in[5];
    const float* b0b   = (const float*)d_in[6];
    const float* wih1f = (const float*)d_in[7];
    const float* whh1f = (const float*)d_in[8];
    const float* b1f   = (const float*)d_in[9];
    const float* wih1b = (const float*)d_in[10];
    const float* whh1b = (const float*)d_in[11];
    const float* b1b   = (const float*)d_in[12];
    (void)in_sizes; (void)n_in; (void)out_size;

    float* out = (float*)d_out;
    float* y1 = out;
    float* hn = out + Y1SZ_;
    float* cn = hn + 4 * B_ * H_;

    const int SMEM_SCAN = G_ * (H_ / 2) * 4 + H_ * BB_ * 4 + G_ * BB_ * 4; // 141,312 B
    cudaFuncSetAttribute(lstm_scan_kernel, cudaFuncAttributeMaxDynamicSharedMemorySize, SMEM_SCAN);

    // x -> fp16 (padded K=32), weights -> fp16
    conv_x_kernel<<<(BT_ * 32 + 255) / 256, 256>>>(x);
    conv_w_kernel<<<(2 * G_ * 32 + 2 * G_ * 256 + 255) / 256, 256>>>(wih0f, wih0b, wih1f, wih1b);

    // layer 0
    gemm_gx_kernel<<<dim3(BT_ / 64, G_ / 128, 2), 256>>>(b0f, b0b, 32);
    lstm_scan_kernel<<<dim3(B_ / BB_, 2), 512, SMEM_SCAN>>>(whh0f, whh0b, y1, hn, cn, 0);

    // layer 1
    conv_h_kernel<<<(int)((Y1SZ_ + 255) / 256), 256>>>();
    gemm_gx_kernel<<<dim3(BT_ / 64, G_ / 128, 2), 256>>>(b1f, b1b, 256);
    lstm_scan_kernel<<<dim3(B_ / BB_, 2), 512, SMEM_SCAN>>>(whh1f, whh1b, y1, hn, cn, 1);
}

// round 2
// speedup vs baseline: 1.8317x; 1.8317x over previous
#include <cuda_runtime.h>
#include <cuda_fp16.h>
#include <cstdint>

#define B_  256
#define T_  512
#define I_  24
#define H_  128
#define G_  512           // 4*H
#define BT_ (B_*T_)       // 131072
#define MB_ 16            // batch rows per scan block (mma M)
#define HAS_ 136          // hA row stride in halves (128 + 8 pad)
#define GS_  520          // gate smem row stride in floats (512 + 8 pad)

static const size_t Y1SZ_ = (size_t)BT_ * 2 * H_;   // 33,554,432

// ---------------- scratch (no cudaMalloc allowed) ----------------
__device__ float  g_gx[2][(size_t)BT_ * G_];        // 2 x 256 MB
__device__ __half g_y0h[(size_t)BT_ * 2 * H_];      // 64 MB (layer-1 input, fp16)
__device__ __half g_xh[(size_t)BT_ * 32];           // x padded 24->32, fp16
__device__ __half g_w0h[2][G_ * 32];                // w_ih layer0 padded, fp16
__device__ __half g_w1h[2][G_ * 256];               // w_ih layer1, fp16

__device__ __forceinline__ float tanhap(float x) {
    float y; asm("tanh.approx.f32 %0, %1;" : "=f"(y) : "f"(x)); return y;
}
__device__ __forceinline__ float sigmap(float x) {
    return fmaf(0.5f, tanhap(0.5f * x), 0.5f);
}

// ---------------- conversion kernels ----------------
__global__ void conv_x_kernel(const float* __restrict__ x) {
    int idx = blockIdx.x * 256 + threadIdx.x;
    if (idx < BT_ * 32) {
        int r = idx >> 5, i = idx & 31;
        g_xh[idx] = (i < I_) ? __float2half(x[r * I_ + i]) : __float2half(0.f);
    }
}

__global__ void conv_w_kernel(const float* __restrict__ w0f, const float* __restrict__ w0b,
                              const float* __restrict__ w1f, const float* __restrict__ w1b) {
    int idx = blockIdx.x * 256 + threadIdx.x;
    if (idx < 2 * G_ * 32) {
        int d = idx / (G_ * 32); int p = idx % (G_ * 32);
        int j = p >> 5, i = p & 31;
        const float* w = d ? w0b : w0f;
        g_w0h[d][p] = (i < I_) ? __float2half(w[j * I_ + i]) : __float2half(0.f);
    } else {
        int q = idx - 2 * G_ * 32;
        if (q < 2 * G_ * 256) {
            int d = q / (G_ * 256); int p = q % (G_ * 256);
            const float* w = d ? w1b : w1f;
            g_w1h[d][p] = __float2half(w[p]);
        }
    }
}

// ---------------- input GEMM: gx[dir][t*B+b][j] = A[r] . W[dir][j] + bias ----------------
__global__ __launch_bounds__(256) void gemm_gx_kernel(
    const float* __restrict__ biasf, const float* __restrict__ biasb, int K)
{
    const int dir = blockIdx.z;
    const __half* __restrict__ A = (K == 32) ? g_xh : g_y0h;
    const __half* __restrict__ W = (K == 32) ? g_w0h[dir] : g_w1h[dir];
    const float* __restrict__ bias = dir ? biasb : biasf;
    float* __restrict__ gx = g_gx[dir];

    const int tid  = threadIdx.x;
    const int lane = tid & 31;
    const int warp = tid >> 5;
    const int warpM = warp & 1;
    const int warpN = warp >> 1;
    const int m_base = blockIdx.x * 64 + warpM * 32;
    const int n_base = blockIdx.y * 128 + warpN * 32;
    const int g4 = lane >> 2;
    const int tg = lane & 3;

    float acc[2][4][4];
    #pragma unroll
    for (int mf = 0; mf < 2; mf++)
        #pragma unroll
        for (int nf = 0; nf < 4; nf++)
            #pragma unroll
            for (int q = 0; q < 4; q++) acc[mf][nf][q] = 0.f;

    for (int k0 = 0; k0 < K; k0 += 16) {
        unsigned a[2][4];
        #pragma unroll
        for (int mf = 0; mf < 2; mf++) {
            const __half* Ap = A + (size_t)(m_base + mf * 16 + g4) * K + k0 + tg * 2;
            a[mf][0] = *(const unsigned*)(Ap);
            a[mf][1] = *(const unsigned*)(Ap + 8 * K);
            a[mf][2] = *(const unsigned*)(Ap + 8);
            a[mf][3] = *(const unsigned*)(Ap + 8 * K + 8);
        }
        #pragma unroll
        for (int nf = 0; nf < 4; nf++) {
            const __half* Wp = W + (size_t)(n_base + nf * 8 + g4) * K + k0 + tg * 2;
            unsigned b0 = *(const unsigned*)(Wp);
            unsigned b1 = *(const unsigned*)(Wp + 8);
            #pragma unroll
            for (int mf = 0; mf < 2; mf++) {
                asm volatile(
                    "mma.sync.aligned.m16n8k16.row.col.f32.f16.f16.f32 "
                    "{%0,%1,%2,%3}, {%4,%5,%6,%7}, {%8,%9}, {%0,%1,%2,%3};"
                    : "+f"(acc[mf][nf][0]), "+f"(acc[mf][nf][1]),
                      "+f"(acc[mf][nf][2]), "+f"(acc[mf][nf][3])
                    : "r"(a[mf][0]), "r"(a[mf][1]), "r"(a[mf][2]), "r"(a[mf][3]),
                      "r"(b0), "r"(b1));
            }
        }
    }

    #pragma unroll
    for (int mf = 0; mf < 2; mf++) {
        int m0 = m_base + mf * 16 + g4;
        #pragma unroll
        for (int nf = 0; nf < 4; nf++) {
            int n0 = n_base + nf * 8 + tg * 2;
            float bv0 = bias[n0], bv1 = bias[n0 + 1];
            int r = m0;
            int t = r & (T_ - 1); int bb = r >> 9;
            size_t o = ((size_t)t * B_ + bb) * G_ + n0;
            gx[o]     = acc[mf][nf][0] + bv0;
            gx[o + 1] = acc[mf][nf][1] + bv1;
            r = m0 + 8;
            t = r & (T_ - 1); bb = r >> 9;
            o = ((size_t)t * B_ + bb) * G_ + n0;
            gx[o]     = acc[mf][nf][2] + bv0;
            gx[o + 1] = acc[mf][nf][3] + bv1;
        }
    }
}

// ---------------- tensor-core recurrent scan ----------------
// grid (16, 2): blockIdx.x = batch group (16 rows), blockIdx.y = direction. 512 threads.
// Per step: gates[16,512] = hA[16,128](fp16,smem) @ Whh^T (fp16, register fragments),
// via mma.m16n8k16. Warp w owns gate columns [w*32, w*32+32).
// Elementwise: thread et owns (b = et>>5, k = (et&31)*4 .. +3).
__global__ __launch_bounds__(512) void lstm_scan_mma(
    const float* __restrict__ whhf, const float* __restrict__ whhb,
    float* __restrict__ y1, float* __restrict__ hn, float* __restrict__ cn, int layer)
{
    __shared__ __half hA[MB_ * HAS_];     // 4352 B
    __shared__ float  gsm[MB_ * GS_];     // 33280 B

    const int tid  = threadIdx.x;
    const int lane = tid & 31;
    const int w    = tid >> 5;            // warp 0..15
    const int dir  = blockIdx.y;
    const int b0   = blockIdx.x * MB_;
    const int g4 = lane >> 2, tg = lane & 3;
    const float* __restrict__ whh = dir ? whhb : whhf;
    const float* __restrict__ gx  = g_gx[dir];

    // preload w_hh fragments into registers (static across all timesteps)
    unsigned Bf[8][4][2];
    {
        const int nb = w * 32;
        #pragma unroll
        for (int ks = 0; ks < 8; ks++)
            #pragma unroll
            for (int nf = 0; nf < 4; nf++) {
                const float* p = whh + (size_t)(nb + nf * 8 + g4) * H_ + ks * 16 + tg * 2;
                float2 v0 = *(const float2*)p;
                float2 v1 = *(const float2*)(p + 8);
                __half2 p0 = __floats2half2_rn(v0.x, v0.y);
                __half2 p1 = __floats2half2_rn(v1.x, v1.y);
                Bf[ks][nf][0] = *(unsigned*)&p0;
                Bf[ks][nf][1] = *(unsigned*)&p1;
            }
    }

    // zero h buffer
    for (int p = tid; p < MB_ * HAS_; p += 512) hA[p] = __float2half(0.f);

    // elementwise ownership
    const int eb = tid >> 5;              // batch row (== warp id)
    const int ek = (lane) * 4;            // k base (4 consecutive)
    float cst[4] = {0.f, 0.f, 0.f, 0.f};
    float hreg[4] = {0.f, 0.f, 0.f, 0.f};

    // ldmatrix A source address (byte offset in shared space)
    const unsigned hA_base = (unsigned)__cvta_generic_to_shared(hA);
    const unsigned lmA = hA_base + (((lane & 15) * HAS_) + ((lane >> 4) * 8)) * 2;

    __syncthreads();

    for (int s = 0; s < T_; s++) {
        const int t = dir ? (T_ - 1 - s) : s;

        // prefetch gx for this step (consumed after the mma phase)
        const float* gxp = gx + ((size_t)t * B_ + b0 + eb) * G_ + ek;
        float4 gxi = *(const float4*)(gxp);
        float4 gxf = *(const float4*)(gxp + 128);
        float4 gxg = *(const float4*)(gxp + 256);
        float4 gxo = *(const float4*)(gxp + 384);

        // ---- phase 1: gates = hA @ Whh^T ----
        float c[4][4];
        #pragma unroll
        for (int nf = 0; nf < 4; nf++)
            #pragma unroll
            for (int q = 0; q < 4; q++) c[nf][q] = 0.f;

        #pragma unroll
        for (int ks = 0; ks < 8; ks++) {
            unsigned a0, a1, a2, a3;
            asm volatile("ldmatrix.sync.aligned.m8n8.x4.shared.b16 {%0,%1,%2,%3}, [%4];"
                : "=r"(a0), "=r"(a1), "=r"(a2), "=r"(a3) : "r"(lmA + ks * 32));
            #pragma unroll
            for (int nf = 0; nf < 4; nf++) {
                asm volatile(
                    "mma.sync.aligned.m16n8k16.row.col.f32.f16.f16.f32 "
                    "{%0,%1,%2,%3}, {%4,%5,%6,%7}, {%8,%9}, {%0,%1,%2,%3};"
                    : "+f"(c[nf][0]), "+f"(c[nf][1]), "+f"(c[nf][2]), "+f"(c[nf][3])
                    : "r"(a0), "r"(a1), "r"(a2), "r"(a3),
                      "r"(Bf[ks][nf][0]), "r"(Bf[ks][nf][1]));
            }
        }

        // scatter C fragments to gate smem
        #pragma unroll
        for (int nf = 0; nf < 4; nf++) {
            int n = w * 32 + nf * 8 + tg * 2;
            *(float2*)&gsm[g4 * GS_ + n]       = make_float2(c[nf][0], c[nf][1]);
            *(float2*)&gsm[(g4 + 8) * GS_ + n] = make_float2(c[nf][2], c[nf][3]);
        }
        __syncthreads();

        // ---- phase 2: elementwise LSTM cell ----
        const float* gr = &gsm[eb * GS_];
        float4 ai = *(const float4*)(gr + ek);
        float4 af = *(const float4*)(gr + 128 + ek);
        float4 ag = *(const float4*)(gr + 256 + ek);
        float4 ao = *(const float4*)(gr + 384 + ek);

        #pragma unroll
        for (int q = 0; q < 4; q++) {
            float gi = ((const float*)&ai)[q] + ((const float*)&gxi)[q];
            float gf = ((const float*)&af)[q] + ((const float*)&gxf)[q];
            float gg = ((const float*)&ag)[q] + ((const float*)&gxg)[q];
            float go = ((const float*)&ao)[q] + ((const float*)&gxo)[q];
            float ii = sigmap(gi), ff = sigmap(gf);
            float gv = tanhap(gg), oo = sigmap(go);
            cst[q] = fmaf(ff, cst[q], ii * gv);
            hreg[q] = oo * tanhap(cst[q]);
        }

        __half2 hp0 = __floats2half2_rn(hreg[0], hreg[1]);
        __half2 hp1 = __floats2half2_rn(hreg[2], hreg[3]);
        *(__half2*)&hA[eb * HAS_ + ek]     = hp0;
        *(__half2*)&hA[eb * HAS_ + ek + 2] = hp1;

        const size_t yoff = ((size_t)(b0 + eb) * T_ + t) * (2 * H_) + dir * H_ + ek;
        if (layer) {
            *(float4*)&y1[yoff] = make_float4(hreg[0], hreg[1], hreg[2], hreg[3]);
        } else {
            __half2 hp[2] = {hp0, hp1};
            *(uint2*)&g_y0h[yoff] = *(uint2*)hp;
        }
        __syncthreads();
    }

    const int d = layer * 2 + dir;
    const size_t so = ((size_t)d * B_ + b0 + eb) * H_ + ek;
    *(float4*)&hn[so] = make_float4(hreg[0], hreg[1], hreg[2], hreg[3]);
    *(float4*)&cn[so] = make_float4(cst[0], cst[1], cst[2], cst[3]);
}

// ---------------- launch ----------------
extern "C" void kernel_launch(void* const* d_in, const int* in_sizes, int n_in,
                              void* d_out, int out_size) {
    const float* x     = (const float*)d_in[0];
    const float* wih0f = (const float*)d_in[1];
    const float* whh0f = (const float*)d_in[2];
    const float* b0f   = (const float*)d_in[3];
    const float* wih0b = (const float*)d_in[4];
    const float* whh0b = (const float*)d_in[5];
    const float* b0b   = (const float*)d_in[6];
    const float* wih1f = (const float*)d_in[7];
    const float* whh1f = (const float*)d_in[8];
    const float* b1f   = (const float*)d_in[9];
    const float* wih1b = (const float*)d_in[10];
    const float* whh1b = (const float*)d_in[11];
    const float* b1b   = (const float*)d_in[12];
    (void)in_sizes; (void)n_in; (void)out_size; (void)wih0f; (void)wih0b; (void)wih1f; (void)wih1b;

    float* out = (float*)d_out;
    float* y1 = out;
    float* hn = out + Y1SZ_;
    float* cn = hn + 4 * B_ * H_;

    // fp16 conversions
    conv_x_kernel<<<(BT_ * 32 + 255) / 256, 256>>>(x);
    conv_w_kernel<<<(2 * G_ * 32 + 2 * G_ * 256 + 255) / 256, 256>>>(wih0f, wih0b, wih1f, wih1b);

    // layer 0
    gemm_gx_kernel<<<dim3(BT_ / 64, G_ / 128, 2), 256>>>(b0f, b0b, 32);
    lstm_scan_mma<<<dim3(B_ / MB_, 2), 512>>>(whh0f, whh0b, y1, hn, cn, 0);

    // layer 1
    gemm_gx_kernel<<<dim3(BT_ / 64, G_ / 128, 2), 256>>>(b1f, b1b, 256);
    lstm_scan_mma<<<dim3(B_ / MB_, 2), 512>>>(whh1f, whh1b, y1, hn, cn, 1);
}

// round 5
// speedup vs baseline: 2.3269x; 1.2704x over previous
#include <cuda_runtime.h>
#include <cuda_fp16.h>
#include <cstdint>

#define B_  256
#define T_  512
#define I_  24
#define H_  128
#define G_  512           // 4*H
#define BT_ (B_*T_)       // 131072
#define MB_ 8             // batch rows per scan block
#define HAS_ 136          // hA row stride in halves (128 + 8 pad)

static const size_t Y1SZ_ = (size_t)BT_ * 2 * H_;   // 33,554,432

// ---------------- scratch (no cudaMalloc allowed) ----------------
// gx fp32, pre-scaled by 0.5 for gates i,f,o. Layout [t][b][j], A-rows t-major.
__device__ float  g_gx[2][(size_t)BT_ * G_];        // 2 x 256 MB
__device__ __half g_y0h[(size_t)BT_ * 2 * H_];      // 64 MB, rows r' = t*B + b
__device__ __half g_xh[(size_t)BT_ * 32];           // x padded 24->32, rows r' = t*B + b
__device__ __half g_w0h[2][G_ * 32];                // w_ih layer0 padded, fp16
__device__ __half g_w1h[2][G_ * 256];               // w_ih layer1, fp16

__device__ __forceinline__ float tanhap(float x) {
    float y; asm("tanh.approx.f32 %0, %1;" : "=f"(y) : "f"(x)); return y;
}

// ---------------- conversion kernels ----------------
__global__ void conv_x_kernel(const float* __restrict__ x) {
    int idx = blockIdx.x * 256 + threadIdx.x;
    if (idx < BT_ * 32) {
        int r = idx >> 5, i = idx & 31;       // r' = t*256 + b
        int b = r & 255, t = r >> 8;
        g_xh[idx] = (i < I_) ? __float2half(x[((size_t)b * T_ + t) * I_ + i]) : __float2half(0.f);
    }
}

__global__ void conv_w_kernel(const float* __restrict__ w0f, const float* __restrict__ w0b,
                              const float* __restrict__ w1f, const float* __restrict__ w1b) {
    int idx = blockIdx.x * 256 + threadIdx.x;
    if (idx < 2 * G_ * 32) {
        int d = idx / (G_ * 32); int p = idx % (G_ * 32);
        int j = p >> 5, i = p & 31;
        const float* w = d ? w0b : w0f;
        g_w0h[d][p] = (i < I_) ? __float2half(w[j * I_ + i]) : __float2half(0.f);
    } else {
        int q = idx - 2 * G_ * 32;
        if (q < 2 * G_ * 256) {
            int d = q / (G_ * 256); int p = q % (G_ * 256);
            const float* w = d ? w1b : w1f;
            g_w1h[d][p] = __float2half(w[p]);
        }
    }
}

// ---------------- input GEMM: gx[dir][t][b][j] = scale(j) * (A[r'] . W[dir][j] + bias) ----------------
__global__ __launch_bounds__(256) void gemm_gx_kernel(
    const float* __restrict__ biasf, const float* __restrict__ biasb, int K)
{
    const int dir = blockIdx.z;
    const __half* __restrict__ A = (K == 32) ? g_xh : g_y0h;
    const __half* __restrict__ W = (K == 32) ? g_w0h[dir] : g_w1h[dir];
    const float* __restrict__ bias = dir ? biasb : biasf;
    float* __restrict__ gx = g_gx[dir];

    const int tid  = threadIdx.x;
    const int lane = tid & 31;
    const int warp = tid >> 5;
    const int warpM = warp & 1;
    const int warpN = warp >> 1;
    const int m_base = blockIdx.x * 64 + warpM * 32;
    const int n_base = blockIdx.y * 128 + warpN * 32;
    const int g4 = lane >> 2;
    const int tg = lane & 3;

    float acc[2][4][4];
    #pragma unroll
    for (int mf = 0; mf < 2; mf++)
        #pragma unroll
        for (int nf = 0; nf < 4; nf++)
            #pragma unroll
            for (int q = 0; q < 4; q++) acc[mf][nf][q] = 0.f;

    for (int k0 = 0; k0 < K; k0 += 16) {
        unsigned a[2][4];
        #pragma unroll
        for (int mf = 0; mf < 2; mf++) {
            const __half* Ap = A + (size_t)(m_base + mf * 16 + g4) * K + k0 + tg * 2;
            a[mf][0] = *(const unsigned*)(Ap);
            a[mf][1] = *(const unsigned*)(Ap + 8 * K);
            a[mf][2] = *(const unsigned*)(Ap + 8);
            a[mf][3] = *(const unsigned*)(Ap + 8 * K + 8);
        }
        #pragma unroll
        for (int nf = 0; nf < 4; nf++) {
            const __half* Wp = W + (size_t)(n_base + nf * 8 + g4) * K + k0 + tg * 2;
            unsigned b0 = *(const unsigned*)(Wp);
            unsigned b1 = *(const unsigned*)(Wp + 8);
            #pragma unroll
            for (int mf = 0; mf < 2; mf++) {
                asm volatile(
                    "mma.sync.aligned.m16n8k16.row.col.f32.f16.f16.f32 "
                    "{%0,%1,%2,%3}, {%4,%5,%6,%7}, {%8,%9}, {%0,%1,%2,%3};"
                    : "+f"(acc[mf][nf][0]), "+f"(acc[mf][nf][1]),
                      "+f"(acc[mf][nf][2]), "+f"(acc[mf][nf][3])
                    : "r"(a[mf][0]), "r"(a[mf][1]), "r"(a[mf][2]), "r"(a[mf][3]),
                      "r"(b0), "r"(b1));
            }
        }
    }

    // epilogue: rows of this M-tile share t; b varies -> contiguous fp32 writes
    #pragma unroll
    for (int mf = 0; mf < 2; mf++) {
        int m0 = m_base + mf * 16 + g4;
        int t  = m0 >> 8;
        int b  = m0 & 255;
        #pragma unroll
        for (int nf = 0; nf < 4; nf++) {
            int n0 = n_base + nf * 8 + tg * 2;
            int g  = n0 >> 7;
            float sc = (g == 2) ? 1.f : 0.5f;
            float bv0 = bias[n0], bv1 = bias[n0 + 1];
            *(float2*)&gx[((size_t)t * B_ + b)     * G_ + n0] =
                make_float2(sc * (acc[mf][nf][0] + bv0), sc * (acc[mf][nf][1] + bv1));
            *(float2*)&gx[((size_t)t * B_ + b + 8) * G_ + n0] =
                make_float2(sc * (acc[mf][nf][2] + bv0), sc * (acc[mf][nf][3] + bv1));
        }
    }
}

// ---------------- tensor-core recurrent scan ----------------
// grid (32, 2). Warp w owns hidden cols [8w, 8w+8) for ALL 4 gates.
// hA DOUBLE-BUFFERED: step s reads buf (s&1), writes buf (s&1)^1 -> the single
// end-of-step barrier is race-free (R3/R4 had a read/write race on one buffer).
__global__ __launch_bounds__(512) void lstm_scan_mma(
    const float* __restrict__ whhf, const float* __restrict__ whhb,
    float* __restrict__ y1, float* __restrict__ hn, float* __restrict__ cn, int layer)
{
    __shared__ __half hA[2 * 16 * HAS_];  // 8704 B, two buffers

    const int tid  = threadIdx.x;
    const int lane = tid & 31;
    const int w    = tid >> 5;            // warp 0..15 -> k-slice
    const int dir  = blockIdx.y;
    const int b0   = blockIdx.x * MB_;
    const int g4 = lane >> 2, tg = lane & 3;
    const float* __restrict__ whh = dir ? whhb : whhf;
    const float* __restrict__ gx  = g_gx[dir];

    // preload w_hh fragments: Bf[ks][g] covers gate cols j = g*128 + 8w .. +8
    unsigned Bf[8][4][2];
    #pragma unroll
    for (int ks = 0; ks < 8; ks++)
        #pragma unroll
        for (int g = 0; g < 4; g++) {
            const float* p = whh + (size_t)(g * 128 + 8 * w + g4) * H_ + ks * 16 + tg * 2;
            float2 v0 = *(const float2*)p;
            float2 v1 = *(const float2*)(p + 8);
            __half2 p0 = __floats2half2_rn(v0.x, v0.y);
            __half2 p1 = __floats2half2_rn(v1.x, v1.y);
            Bf[ks][g][0] = *(unsigned*)&p0;
            Bf[ks][g][1] = *(unsigned*)&p1;
        }

    for (int p = tid; p < 2 * 16 * HAS_; p += 512) hA[p] = __float2half(0.f);

    const int col  = 8 * w + 2 * tg;      // hidden col base (2 cols per thread)
    const int brow = b0 + g4;             // batch row owned in cell phase
    float cst0 = 0.f, cst1 = 0.f;
    float h0 = 0.f, h1 = 0.f;

    const unsigned hA_base = (unsigned)__cvta_generic_to_shared(hA);
    const unsigned lmA = hA_base + (((lane & 15) * HAS_) + ((lane >> 4) * 8)) * 2;
    const unsigned BUFB = 16 * HAS_ * 2;  // buffer stride in bytes

    __syncthreads();

    // prefetch gx for first step
    float2 gxc0, gxc1, gxc2, gxc3;
    {
        int t0 = dir ? (T_ - 1) : 0;
        const float* p = gx + ((size_t)t0 * B_ + brow) * G_ + col;
        gxc0 = *(const float2*)(p);
        gxc1 = *(const float2*)(p + 128);
        gxc2 = *(const float2*)(p + 256);
        gxc3 = *(const float2*)(p + 384);
    }

    for (int s = 0; s < T_; s++) {
        const int t = dir ? (T_ - 1 - s) : s;
        const int rb = s & 1;             // read buffer
        const unsigned lm = lmA + rb * BUFB;
        __half* hw = hA + (rb ^ 1) * 16 * HAS_;   // write buffer

        // prefetch next step's gx
        float2 gxn0, gxn1, gxn2, gxn3;
        if (s + 1 < T_) {
            int tn = dir ? (T_ - 2 - s) : (s + 1);
            const float* p = gx + ((size_t)tn * B_ + brow) * G_ + col;
            gxn0 = *(const float2*)(p);
            gxn1 = *(const float2*)(p + 128);
            gxn2 = *(const float2*)(p + 256);
            gxn3 = *(const float2*)(p + 384);
        } else {
            gxn0 = gxn1 = gxn2 = gxn3 = make_float2(0.f, 0.f);
        }

        // ---- gates = hA[rb] @ Whh^T ----
        float c[4][4];
        #pragma unroll
        for (int g = 0; g < 4; g++)
            #pragma unroll
            for (int q = 0; q < 4; q++) c[g][q] = 0.f;

        #pragma unroll
        for (int ks = 0; ks < 8; ks++) {
            unsigned a0, a1, a2, a3;
            asm volatile("ldmatrix.sync.aligned.m8n8.x4.shared.b16 {%0,%1,%2,%3}, [%4];"
                : "=r"(a0), "=r"(a1), "=r"(a2), "=r"(a3) : "r"(lm + ks * 32));
            #pragma unroll
            for (int g = 0; g < 4; g++) {
                asm volatile(
                    "mma.sync.aligned.m16n8k16.row.col.f32.f16.f16.f32 "
                    "{%0,%1,%2,%3}, {%4,%5,%6,%7}, {%8,%9}, {%0,%1,%2,%3};"
                    : "+f"(c[g][0]), "+f"(c[g][1]), "+f"(c[g][2]), "+f"(c[g][3])
                    : "r"(a0), "r"(a1), "r"(a2), "r"(a3),
                      "r"(Bf[ks][g][0]), "r"(Bf[ks][g][1]));
            }
        }

        // ---- in-register LSTM cell (2 cells per thread) ----
        // gx for i,f,o is pre-scaled by 0.5 (sigm(x) = 0.5*tanh(0.5x)+0.5)
        float ii0 = fmaf(tanhap(fmaf(c[0][0], 0.5f, gxc0.x)), 0.5f, 0.5f);
        float ii1 = fmaf(tanhap(fmaf(c[0][1], 0.5f, gxc0.y)), 0.5f, 0.5f);
        float ff0 = fmaf(tanhap(fmaf(c[1][0], 0.5f, gxc1.x)), 0.5f, 0.5f);
        float ff1 = fmaf(tanhap(fmaf(c[1][1], 0.5f, gxc1.y)), 0.5f, 0.5f);
        float gg0 = tanhap(c[2][0] + gxc2.x);
        float gg1 = tanhap(c[2][1] + gxc2.y);
        float oo0 = fmaf(tanhap(fmaf(c[3][0], 0.5f, gxc3.x)), 0.5f, 0.5f);
        float oo1 = fmaf(tanhap(fmaf(c[3][1], 0.5f, gxc3.y)), 0.5f, 0.5f);

        cst0 = fmaf(ff0, cst0, ii0 * gg0);
        cst1 = fmaf(ff1, cst1, ii1 * gg1);
        h0 = oo0 * tanhap(cst0);
        h1 = oo1 * tanhap(cst1);

        __half2 hp = __floats2half2_rn(h0, h1);
        *(__half2*)&hw[g4 * HAS_ + col] = hp;

        if (layer) {
            *(float2*)&y1[((size_t)brow * T_ + t) * (2 * H_) + dir * H_ + col] = make_float2(h0, h1);
        } else {
            *(__half2*)&g_y0h[((size_t)t * B_ + brow) * (2 * H_) + dir * H_ + col] = hp;
        }

        gxc0 = gxn0; gxc1 = gxn1; gxc2 = gxn2; gxc3 = gxn3;
        __syncthreads();   // step-s writes visible before step-s+1 reads
    }

    const int d = layer * 2 + dir;
    const size_t so = ((size_t)d * B_ + brow) * H_ + col;
    *(float2*)&hn[so] = make_float2(h0, h1);
    *(float2*)&cn[so] = make_float2(cst0, cst1);
}

// ---------------- launch ----------------
extern "C" void kernel_launch(void* const* d_in, const int* in_sizes, int n_in,
                              void* d_out, int out_size) {
    const float* x     = (const float*)d_in[0];
    const float* wih0f = (const float*)d_in[1];
    const float* whh0f = (const float*)d_in[2];
    const float* b0f   = (const float*)d_in[3];
    const float* wih0b = (const float*)d_in[4];
    const float* whh0b = (const float*)d_in[5];
    const float* b0b   = (const float*)d_in[6];
    const float* wih1f = (const float*)d_in[7];
    const float* whh1f = (const float*)d_in[8];
    const float* b1f   = (const float*)d_in[9];
    const float* wih1b = (const float*)d_in[10];
    const float* whh1b = (const float*)d_in[11];
    const float* b1b   = (const float*)d_in[12];
    (void)in_sizes; (void)n_in; (void)out_size;

    float* out = (float*)d_out;
    float* y1 = out;
    float* hn = out + Y1SZ_;
    float* cn = hn + 4 * B_ * H_;

    // fp16 conversions
    conv_x_kernel<<<(BT_ * 32 + 255) / 256, 256>>>(x);
    conv_w_kernel<<<(2 * G_ * 32 + 2 * G_ * 256 + 255) / 256, 256>>>(wih0f, wih0b, wih1f, wih1b);

    // layer 0
    gemm_gx_kernel<<<dim3(BT_ / 64, G_ / 128, 2), 256>>>(b0f, b0b, 32);
    lstm_scan_mma<<<dim3(B_ / MB_, 2), 512>>>(whh0f, whh0b, y1, hn, cn, 0);

    // layer 1
    gemm_gx_kernel<<<dim3(BT_ / 64, G_ / 128, 2), 256>>>(b1f, b1b, 256);
    lstm_scan_mma<<<dim3(B_ / MB_, 2), 512>>>(whh1f, whh1b, y1, hn, cn, 1);
}

// round 6
// speedup vs baseline: 3.5891x; 1.5424x over previous
#include <cuda_runtime.h>
#include <cuda_fp16.h>
#include <cstdint>

#define B_  256
#define T_  512
#define I_  24
#define H_  128
#define G_  512           // 4*H
#define BT_ (B_*T_)       // 131072
#define MB_ 8             // batch rows per scan block
#define HAS_ 136          // hA row stride in halves (128 + 8 pad)
#define SAS_ 40           // GEMM smem row stride in halves (32 + 8 pad)

static const size_t Y1SZ_ = (size_t)BT_ * 2 * H_;   // 33,554,432

// ---------------- scratch (no cudaMalloc allowed) ----------------
// gx fp32, pre-scaled by 0.5 for gates i,f,o. Layout [t][b][j], A-rows t-major.
__device__ float  g_gx[2][(size_t)BT_ * G_];        // 2 x 256 MB
__device__ __half g_y0h[(size_t)BT_ * 2 * H_];      // 64 MB, rows r' = t*B + b
__device__ __half g_xh[(size_t)BT_ * 32];           // x padded 24->32, rows r' = t*B + b
__device__ __half g_w0h[2][G_ * 32];                // w_ih layer0 padded, fp16
__device__ __half g_w1h[2][G_ * 256];               // w_ih layer1, fp16

__device__ __forceinline__ float tanhap(float x) {
    float y; asm("tanh.approx.f32 %0, %1;" : "=f"(y) : "f"(x)); return y;
}
__device__ __forceinline__ void cp16(unsigned dst, const void* src) {
    asm volatile("cp.async.ca.shared.global [%0], [%1], 16;" :: "r"(dst), "l"(src));
}

// ---------------- conversion kernels ----------------
__global__ void conv_x_kernel(const float* __restrict__ x) {
    int idx = blockIdx.x * 256 + threadIdx.x;
    if (idx < BT_ * 32) {
        int r = idx >> 5, i = idx & 31;       // r' = t*256 + b
        int b = r & 255, t = r >> 8;
        g_xh[idx] = (i < I_) ? __float2half(x[((size_t)b * T_ + t) * I_ + i]) : __float2half(0.f);
    }
}

__global__ void conv_w_kernel(const float* __restrict__ w0f, const float* __restrict__ w0b,
                              const float* __restrict__ w1f, const float* __restrict__ w1b) {
    int idx = blockIdx.x * 256 + threadIdx.x;
    if (idx < 2 * G_ * 32) {
        int d = idx / (G_ * 32); int p = idx % (G_ * 32);
        int j = p >> 5, i = p & 31;
        const float* w = d ? w0b : w0f;
        g_w0h[d][p] = (i < I_) ? __float2half(w[j * I_ + i]) : __float2half(0.f);
    } else {
        int q = idx - 2 * G_ * 32;
        if (q < 2 * G_ * 256) {
            int d = q / (G_ * 256); int p = q % (G_ * 256);
            const float* w = d ? w1b : w1f;
            g_w1h[d][p] = __float2half(w[p]);
        }
    }
}

// ---------------- pipelined input GEMM ----------------
// gx[dir][t][b][j] = scale(j) * (A[r'] . W[dir][j] + bias[j]),  r' = t*B + b.
// Block tile 128(M) x 128(N), K-chunk 32, cp.async double-buffered smem stages,
// ldmatrix fragment loads, 8 warps (4M x 2N), mma m16n8k16.
__global__ __launch_bounds__(256) void gemm_gx_kernel(
    const float* __restrict__ biasf, const float* __restrict__ biasb, int K)
{
    __shared__ __half sA[2][128 * SAS_];   // 20 KB
    __shared__ __half sW[2][128 * SAS_];   // 20 KB

    const int dir = blockIdx.z;
    const __half* __restrict__ A = (K == 32) ? g_xh : g_y0h;
    const __half* __restrict__ W = (K == 32) ? g_w0h[dir] : g_w1h[dir];
    const float* __restrict__ bias = dir ? biasb : biasf;
    float* __restrict__ gx = g_gx[dir];

    const int tid  = threadIdx.x;
    const int lane = tid & 31;
    const int warp = tid >> 5;
    const int warpM = warp & 3;           // 4 M-warps x 32 rows
    const int warpN = warp >> 2;          // 2 N-warps x 64 cols
    const int g4 = lane >> 2;
    const int tg = lane & 3;
    const int mblk = blockIdx.x * 128;    // A row base
    const int nblk = blockIdx.y * 128;    // gate col base
    const int nk = K >> 5;                // stages

    const unsigned sA_base = (unsigned)__cvta_generic_to_shared(sA);
    const unsigned sW_base = (unsigned)__cvta_generic_to_shared(sW);

    // loader: 256 threads, 2 rows each (64B = 4x16B segs per row, 4 thr/row)
    const int lrow = tid >> 2;            // 0..63
    const int lseg = tid & 3;

    auto load_stage = [&](int ks, int buf) {
        #pragma unroll
        for (int rr = 0; rr < 2; rr++) {
            int r = lrow + rr * 64;
            const __half* srcA = A + (size_t)(mblk + r) * K + ks * 32 + lseg * 8;
            const __half* srcW = W + (size_t)(nblk + r) * K + ks * 32 + lseg * 8;
            unsigned off = (unsigned)(buf * 128 * SAS_ + r * SAS_ + lseg * 8) * 2;
            cp16(sA_base + off, srcA);
            cp16(sW_base + off, srcW);
        }
        asm volatile("cp.async.commit_group;");
    };

    float acc[2][8][4];
    #pragma unroll
    for (int mf = 0; mf < 2; mf++)
        #pragma unroll
        for (int nf = 0; nf < 8; nf++)
            #pragma unroll
            for (int q = 0; q < 4; q++) acc[mf][nf][q] = 0.f;

    load_stage(0, 0);

    // ldmatrix source addresses (per-lane, within a buffer)
    // A x4: rows warpM*32 + mf*16 + (lane&15), col 8*(lane>>4) + kk*16
    // W x2: rows warpN*64 + nf*8 + (lane&7),  col 8*((lane>>3)&1) + kk*16
    const unsigned lmA0 = sA_base + ((warpM * 32 + (lane & 15)) * SAS_ + (lane >> 4) * 8) * 2;
    const unsigned lmW0 = sW_base + ((warpN * 64 + (lane & 7)) * SAS_ + ((lane >> 3) & 1) * 8) * 2;

    for (int ks = 0; ks < nk; ks++) {
        const int buf = ks & 1;
        if (ks + 1 < nk) {
            load_stage(ks + 1, buf ^ 1);
            asm volatile("cp.async.wait_group 1;");
        } else {
            asm volatile("cp.async.wait_group 0;");
        }
        __syncthreads();

        const unsigned aBuf = lmA0 + buf * 128 * SAS_ * 2;
        const unsigned wBuf = lmW0 + buf * 128 * SAS_ * 2;

        #pragma unroll
        for (int kk = 0; kk < 2; kk++) {
            unsigned a[2][4];
            #pragma unroll
            for (int mf = 0; mf < 2; mf++) {
                asm volatile("ldmatrix.sync.aligned.m8n8.x4.shared.b16 {%0,%1,%2,%3}, [%4];"
                    : "=r"(a[mf][0]), "=r"(a[mf][1]), "=r"(a[mf][2]), "=r"(a[mf][3])
                    : "r"(aBuf + (mf * 16 * SAS_ + kk * 16) * 2));
            }
            #pragma unroll
            for (int nf = 0; nf < 8; nf++) {
                unsigned b0, b1;
                asm volatile("ldmatrix.sync.aligned.m8n8.x2.shared.b16 {%0,%1}, [%2];"
                    : "=r"(b0), "=r"(b1)
                    : "r"(wBuf + (nf * 8 * SAS_ + kk * 16) * 2));
                #pragma unroll
                for (int mf = 0; mf < 2; mf++) {
                    asm volatile(
                        "mma.sync.aligned.m16n8k16.row.col.f32.f16.f16.f32 "
                        "{%0,%1,%2,%3}, {%4,%5,%6,%7}, {%8,%9}, {%0,%1,%2,%3};"
                        : "+f"(acc[mf][nf][0]), "+f"(acc[mf][nf][1]),
                          "+f"(acc[mf][nf][2]), "+f"(acc[mf][nf][3])
                        : "r"(a[mf][0]), "r"(a[mf][1]), "r"(a[mf][2]), "r"(a[mf][3]),
                          "r"(b0), "r"(b1));
                }
            }
        }
        __syncthreads();
    }

    // epilogue: all rows of this block share t; b varies -> coalesced fp32 writes
    const int t = mblk >> 8;
    #pragma unroll
    for (int mf = 0; mf < 2; mf++) {
        int m = warpM * 32 + mf * 16 + g4;
        int b = (mblk & 255) + m;
        #pragma unroll
        for (int nf = 0; nf < 8; nf++) {
            int n0 = nblk + warpN * 64 + nf * 8 + tg * 2;
            float sc = ((n0 >> 7) == 2) ? 1.f : 0.5f;
            float bv0 = bias[n0], bv1 = bias[n0 + 1];
            *(float2*)&gx[((size_t)t * B_ + b)     * G_ + n0] =
                make_float2(sc * (acc[mf][nf][0] + bv0), sc * (acc[mf][nf][1] + bv1));
            *(float2*)&gx[((size_t)t * B_ + b + 8) * G_ + n0] =
                make_float2(sc * (acc[mf][nf][2] + bv0), sc * (acc[mf][nf][3] + bv1));
        }
    }
}

// ---------------- tensor-core recurrent scan (unchanged, verified) ----------------
__global__ __launch_bounds__(512) void lstm_scan_mma(
    const float* __restrict__ whhf, const float* __restrict__ whhb,
    float* __restrict__ y1, float* __restrict__ hn, float* __restrict__ cn, int layer)
{
    __shared__ __half hA[2 * 16 * HAS_];  // 8704 B, two buffers

    const int tid  = threadIdx.x;
    const int lane = tid & 31;
    const int w    = tid >> 5;            // warp 0..15 -> k-slice
    const int dir  = blockIdx.y;
    const int b0   = blockIdx.x * MB_;
    const int g4 = lane >> 2, tg = lane & 3;
    const float* __restrict__ whh = dir ? whhb : whhf;
    const float* __restrict__ gx  = g_gx[dir];

    unsigned Bf[8][4][2];
    #pragma unroll
    for (int ks = 0; ks < 8; ks++)
        #pragma unroll
        for (int g = 0; g < 4; g++) {
            const float* p = whh + (size_t)(g * 128 + 8 * w + g4) * H_ + ks * 16 + tg * 2;
            float2 v0 = *(const float2*)p;
            float2 v1 = *(const float2*)(p + 8);
            __half2 p0 = __floats2half2_rn(v0.x, v0.y);
            __half2 p1 = __floats2half2_rn(v1.x, v1.y);
            Bf[ks][g][0] = *(unsigned*)&p0;
            Bf[ks][g][1] = *(unsigned*)&p1;
        }

    for (int p = tid; p < 2 * 16 * HAS_; p += 512) hA[p] = __float2half(0.f);

    const int col  = 8 * w + 2 * tg;
    const int brow = b0 + g4;
    float cst0 = 0.f, cst1 = 0.f;
    float h0 = 0.f, h1 = 0.f;

    const unsigned hA_base = (unsigned)__cvta_generic_to_shared(hA);
    const unsigned lmA = hA_base + (((lane & 15) * HAS_) + ((lane >> 4) * 8)) * 2;
    const unsigned BUFB = 16 * HAS_ * 2;

    __syncthreads();

    float2 gxc0, gxc1, gxc2, gxc3;
    {
        int t0 = dir ? (T_ - 1) : 0;
        const float* p = gx + ((size_t)t0 * B_ + brow) * G_ + col;
        gxc0 = *(const float2*)(p);
        gxc1 = *(const float2*)(p + 128);
        gxc2 = *(const float2*)(p + 256);
        gxc3 = *(const float2*)(p + 384);
    }

    for (int s = 0; s < T_; s++) {
        const int t = dir ? (T_ - 1 - s) : s;
        const int rb = s & 1;
        const unsigned lm = lmA + rb * BUFB;
        __half* hw = hA + (rb ^ 1) * 16 * HAS_;

        float2 gxn0, gxn1, gxn2, gxn3;
        if (s + 1 < T_) {
            int tn = dir ? (T_ - 2 - s) : (s + 1);
            const float* p = gx + ((size_t)tn * B_ + brow) * G_ + col;
            gxn0 = *(const float2*)(p);
            gxn1 = *(const float2*)(p + 128);
            gxn2 = *(const float2*)(p + 256);
            gxn3 = *(const float2*)(p + 384);
        } else {
            gxn0 = gxn1 = gxn2 = gxn3 = make_float2(0.f, 0.f);
        }

        float c[4][4];
        #pragma unroll
        for (int g = 0; g < 4; g++)
            #pragma unroll
            for (int q = 0; q < 4; q++) c[g][q] = 0.f;

        #pragma unroll
        for (int ks = 0; ks < 8; ks++) {
            unsigned a0, a1, a2, a3;
            asm volatile("ldmatrix.sync.aligned.m8n8.x4.shared.b16 {%0,%1,%2,%3}, [%4];"
                : "=r"(a0), "=r"(a1), "=r"(a2), "=r"(a3) : "r"(lm + ks * 32));
            #pragma unroll
            for (int g = 0; g < 4; g++) {
                asm volatile(
                    "mma.sync.aligned.m16n8k16.row.col.f32.f16.f16.f32 "
                    "{%0,%1,%2,%3}, {%4,%5,%6,%7}, {%8,%9}, {%0,%1,%2,%3};"
                    : "+f"(c[g][0]), "+f"(c[g][1]), "+f"(c[g][2]), "+f"(c[g][3])
                    : "r"(a0), "r"(a1), "r"(a2), "r"(a3),
                      "r"(Bf[ks][g][0]), "r"(Bf[ks][g][1]));
            }
        }

        float ii0 = fmaf(tanhap(fmaf(c[0][0], 0.5f, gxc0.x)), 0.5f, 0.5f);
        float ii1 = fmaf(tanhap(fmaf(c[0][1], 0.5f, gxc0.y)), 0.5f, 0.5f);
        float ff0 = fmaf(tanhap(fmaf(c[1][0], 0.5f, gxc1.x)), 0.5f, 0.5f);
        float ff1 = fmaf(tanhap(fmaf(c[1][1], 0.5f, gxc1.y)), 0.5f, 0.5f);
        float gg0 = tanhap(c[2][0] + gxc2.x);
        float gg1 = tanhap(c[2][1] + gxc2.y);
        float oo0 = fmaf(tanhap(fmaf(c[3][0], 0.5f, gxc3.x)), 0.5f, 0.5f);
        float oo1 = fmaf(tanhap(fmaf(c[3][1], 0.5f, gxc3.y)), 0.5f, 0.5f);

        cst0 = fmaf(ff0, cst0, ii0 * gg0);
        cst1 = fmaf(ff1, cst1, ii1 * gg1);
        h0 = oo0 * tanhap(cst0);
        h1 = oo1 * tanhap(cst1);

        __half2 hp = __floats2half2_rn(h0, h1);
        *(__half2*)&hw[g4 * HAS_ + col] = hp;

        if (layer) {
            *(float2*)&y1[((size_t)brow * T_ + t) * (2 * H_) + dir * H_ + col] = make_float2(h0, h1);
        } else {
            *(__half2*)&g_y0h[((size_t)t * B_ + brow) * (2 * H_) + dir * H_ + col] = hp;
        }

        gxc0 = gxn0; gxc1 = gxn1; gxc2 = gxn2; gxc3 = gxn3;
        __syncthreads();
    }

    const int d = layer * 2 + dir;
    const size_t so = ((size_t)d * B_ + brow) * H_ + col;
    *(float2*)&hn[so] = make_float2(h0, h1);
    *(float2*)&cn[so] = make_float2(cst0, cst1);
}

// ---------------- launch ----------------
extern "C" void kernel_launch(void* const* d_in, const int* in_sizes, int n_in,
                              void* d_out, int out_size) {
    const float* x     = (const float*)d_in[0];
    const float* wih0f = (const float*)d_in[1];
    const float* whh0f = (const float*)d_in[2];
    const float* b0f   = (const float*)d_in[3];
    const float* wih0b = (const float*)d_in[4];
    const float* whh0b = (const float*)d_in[5];
    const float* b0b   = (const float*)d_in[6];
    const float* wih1f = (const float*)d_in[7];
    const float* whh1f = (const float*)d_in[8];
    const float* b1f   = (const float*)d_in[9];
    const float* wih1b = (const float*)d_in[10];
    const float* whh1b = (const float*)d_in[11];
    const float* b1b   = (const float*)d_in[12];
    (void)in_sizes; (void)n_in; (void)out_size;

    float* out = (float*)d_out;
    float* y1 = out;
    float* hn = out + Y1SZ_;
    float* cn = hn + 4 * B_ * H_;

    // fp16 conversions
    conv_x_kernel<<<(BT_ * 32 + 255) / 256, 256>>>(x);
    conv_w_kernel<<<(2 * G_ * 32 + 2 * G_ * 256 + 255) / 256, 256>>>(wih0f, wih0b, wih1f, wih1b);

    // layer 0
    gemm_gx_kernel<<<dim3(BT_ / 128, G_ / 128, 2), 256>>>(b0f, b0b, 32);
    lstm_scan_mma<<<dim3(B_ / MB_, 2), 512>>>(whh0f, whh0b, y1, hn, cn, 0);

    // layer 1
    gemm_gx_kernel<<<dim3(BT_ / 128, G_ / 128, 2), 256>>>(b1f, b1b, 256);
    lstm_scan_mma<<<dim3(B_ / MB_, 2), 512>>>(whh1f, whh1b, y1, hn, cn, 1);
}